// round 13
// baseline (speedup 1.0000x reference)
#include <cuda_runtime.h>
#include <cuda_fp16.h>
#include <mma.h>
#include <cstdint>

using namespace nvcuda;

#define N_USERS    50000
#define N_ENTITIES 150000
#define N_NODES    200000
#define N_EDGES    3200000
#define BATCH      4096
#define SCAN_BLOCKS 196            // 196*1024 = 200704 >= N_NODES

// ---------------- scratch (device globals; no allocation allowed) ----------
__device__ __align__(16) __half g_hneigh16[(size_t)N_NODES * 64]; // fp16 neighbor sums
__device__ __align__(16) float  g_h1[(size_t)N_NODES * 64];
__device__ __align__(16) float  g_h2[(size_t)N_NODES * 32];
__device__ __align__(16) __half g_feat16[(size_t)N_NODES * 64];  // fp16 ego features
__device__ __align__(16) __half g_h116[(size_t)N_NODES * 64];    // fp16 copy of h1
__device__ __align__(16) int    g_count[N_NODES];
__device__ __align__(16) int    g_rowstart[N_NODES + 4];
__device__ __align__(16) int    g_cursor[N_NODES + 4];
__device__ __align__(16) int    g_bsum[SCAN_BLOCKS];
__device__ __align__(16) int    g_boff[SCAN_BLOCKS];
__device__ int                  g_ticket;
__device__ __align__(16) int2   g_srt[N_EDGES];     // {neighbor, value-bits} sorted by target

__device__ __forceinline__ const float* feat0_row(const float* uw, const float* ew, int n) {
    return (n < N_USERS) ? (uw + (size_t)n * 64) : (ew + (size_t)(n - N_USERS) * 64);
}

// ---------------- fp16 feature table build (+ zero counts, ticket) ---------
__global__ void __launch_bounds__(256) k_tofp16(const float* __restrict__ uw,
                                                const float* __restrict__ ew) {
    size_t i = (size_t)blockIdx.x * 256 + threadIdx.x;
    if (i < N_NODES / 4) ((int4*)g_count)[i] = make_int4(0, 0, 0, 0);
    if (i == 0) g_ticket = 0;
    size_t base = i * 8;
    int node = (int)(base >> 6);
    int col  = (int)(base & 63);
    const float* row = feat0_row(uw, ew, node);
    float4 a = *(const float4*)(row + col);
    float4 b = *(const float4*)(row + col + 4);
    __half2 h0 = __floats2half2_rn(a.x, a.y);
    __half2 h1 = __floats2half2_rn(a.z, a.w);
    __half2 h2 = __floats2half2_rn(b.x, b.y);
    __half2 h3 = __floats2half2_rn(b.z, b.w);
    uint4 out;
    out.x = *(const unsigned*)&h0;
    out.y = *(const unsigned*)&h1;
    out.z = *(const unsigned*)&h2;
    out.w = *(const unsigned*)&h3;
    *(uint4*)(g_feat16 + base) = out;
}

// ---------------- CSR build ------------------------------------------------
__global__ void __launch_bounds__(256) k_count(const int* __restrict__ target) {
    int e4 = blockIdx.x * 256 + threadIdx.x;          // grid exact: 800000/256
    int4 t = __ldcs((const int4*)target + e4);
    atomicAdd(&g_count[t.x], 1);
    atomicAdd(&g_count[t.y], 1);
    atomicAdd(&g_count[t.z], 1);
    atomicAdd(&g_count[t.w], 1);
}

// Phase 1: per-block exclusive scan of 1024 counts; last block also scans
// the 196 block totals into g_boff (ticket pattern).
__global__ void __launch_bounds__(1024) k_scan1() {
    __shared__ int warp_tot[32];
    __shared__ int isLast;
    int i = blockIdx.x * 1024 + threadIdx.x;
    int lane = threadIdx.x & 31, w = threadIdx.x >> 5;
    int v = (i < N_NODES) ? g_count[i] : 0;
    int x = v;
    #pragma unroll
    for (int o = 1; o < 32; o <<= 1) {
        int y = __shfl_up_sync(0xffffffffu, x, o);
        if (lane >= o) x += y;
    }
    if (lane == 31) warp_tot[w] = x;
    if (threadIdx.x == 0) isLast = 0;
    __syncthreads();
    if (w == 0) {
        int t = warp_tot[lane];
        #pragma unroll
        for (int o = 1; o < 32; o <<= 1) {
            int y = __shfl_up_sync(0xffffffffu, t, o);
            if (lane >= o) t += y;
        }
        warp_tot[lane] = t;
    }
    __syncthreads();
    int excl = x - v + ((w > 0) ? warp_tot[w - 1] : 0);
    if (i < N_NODES) g_rowstart[i] = excl;
    if (threadIdx.x == 1023) {
        g_bsum[blockIdx.x] = excl + v;
        __threadfence();
        int tkt = atomicAdd(&g_ticket, 1);
        if (tkt == SCAN_BLOCKS - 1) isLast = 1;
    }
    __syncthreads();
    if (isLast) {                                     // uniform per block
        int t = threadIdx.x;
        int val = (t < SCAN_BLOCKS) ? __ldcg(&g_bsum[t]) : 0;
        int x2 = val;
        #pragma unroll
        for (int o = 1; o < 32; o <<= 1) {
            int y = __shfl_up_sync(0xffffffffu, x2, o);
            if (lane >= o) x2 += y;
        }
        if (lane == 31) warp_tot[w] = x2;
        __syncthreads();
        if (t < SCAN_BLOCKS) {
            int off = 0;
            for (int k = 0; k < w; k++) off += warp_tot[k];
            g_boff[t] = x2 - val + off;
        }
    }
}

// Phase 3: add block offsets.
__global__ void __launch_bounds__(1024) k_scan3() {
    int i = blockIdx.x * 1024 + threadIdx.x;
    if (i < N_NODES) {
        int v = g_rowstart[i] + g_boff[blockIdx.x];
        g_rowstart[i] = v;
        g_cursor[i]   = v;
    }
    if (i == 0) g_rowstart[N_NODES] = N_EDGES;
}

__global__ void __launch_bounds__(256) k_scatter(const int* __restrict__ target,
                                                const int* __restrict__ neighbor,
                                                const float* __restrict__ values) {
    int e = blockIdx.x * 256 + threadIdx.x;           // grid exact
    int t = __ldcs(target + e);
    int2 rec = make_int2(__ldcs(neighbor + e), __float_as_int(__ldcs(values + e)));
    int pos = atomicAdd(&g_cursor[t], 1);
    __stcs((int2*)&g_srt[pos], rec);
}

// ---------------- CSR gather (fp16 rows, 4 edges in flight) ----------------
// One warp per node: 16 lanes x uint2 cover the 128B fp16 row; the two
// halves take alternate edge pairs. Each half processes edges i and i+2
// concurrently (2 accumulators, 2 feature rows in flight) with the next
// record pair prefetched. 16 sectors in flight per warp.
template <int LAYER>
__global__ void __launch_bounds__(256) k_gather() {
    int n = (blockIdx.x * 256 + threadIdx.x) >> 5;    // grid exact: 25000*8 warps
    int lane = threadIdx.x & 31;
    int c = lane & 15, half = lane >> 4;
    const __half* TAB = (LAYER == 1) ? g_feat16 : g_h116;
    int base = g_rowstart[n];
    int end  = g_rowstart[n + 1];
    float4 acc0 = make_float4(0.f, 0.f, 0.f, 0.f);
    float4 acc1 = acc0;
    int i = base + half;
    int2 e0 = (i     < end) ? __ldcs(&g_srt[i])     : make_int2(0, 0);
    int2 e1 = (i + 2 < end) ? __ldcs(&g_srt[i + 2]) : make_int2(0, 0);
    for (; i < end; i += 4) {
        int2 c0 = e0, c1 = e1;
        bool has1 = (i + 2 < end);
        if (i + 4 < end) e0 = __ldcs(&g_srt[i + 4]);  // prefetch next pair
        if (i + 6 < end) e1 = __ldcs(&g_srt[i + 6]);
        float v0 = __int_as_float(c0.y);
        float v1 = has1 ? __int_as_float(c1.y) : 0.f;
        int  n1 = has1 ? c1.x : c0.x;                 // safe address
        uint2 hv0 = *(const uint2*)(TAB + (size_t)c0.x * 64 + c * 4);
        uint2 hv1 = *(const uint2*)(TAB + (size_t)n1   * 64 + c * 4);
        float2 a01 = __half22float2(*(const __half2*)&hv0.x);
        float2 a23 = __half22float2(*(const __half2*)&hv0.y);
        float2 b01 = __half22float2(*(const __half2*)&hv1.x);
        float2 b23 = __half22float2(*(const __half2*)&hv1.y);
        acc0.x = fmaf(a01.x, v0, acc0.x);
        acc0.y = fmaf(a01.y, v0, acc0.y);
        acc0.z = fmaf(a23.x, v0, acc0.z);
        acc0.w = fmaf(a23.y, v0, acc0.w);
        acc1.x = fmaf(b01.x, v1, acc1.x);
        acc1.y = fmaf(b01.y, v1, acc1.y);
        acc1.z = fmaf(b23.x, v1, acc1.z);
        acc1.w = fmaf(b23.y, v1, acc1.w);
    }
    acc0.x += acc1.x; acc0.y += acc1.y; acc0.z += acc1.z; acc0.w += acc1.w;
    acc0.x += __shfl_xor_sync(0xffffffffu, acc0.x, 16);
    acc0.y += __shfl_xor_sync(0xffffffffu, acc0.y, 16);
    acc0.z += __shfl_xor_sync(0xffffffffu, acc0.z, 16);
    acc0.w += __shfl_xor_sync(0xffffffffu, acc0.w, 16);
    if (half == 0) {
        __half2 a01 = __floats2half2_rn(acc0.x, acc0.y);
        __half2 a23 = __floats2half2_rn(acc0.z, acc0.w);
        int2 st = make_int2(*(const int*)&a01, *(const int*)&a23);
        __stcs((int2*)(g_hneigh16 + (size_t)n * 64 + c * 4), st);
    }
}

// ---------------- dense layers via wmma (fp16 x fp16 -> fp32) --------------
// f and g both fp16; s/p via __hadd2/__hmul2.
template <int LAYER>
__global__ void __launch_bounds__(256) k_dense(const float* __restrict__ W1,
                                               const float* __restrict__ b1,
                                               const float* __restrict__ W2,
                                               const float* __restrict__ b2) {
    constexpr int NOUT = (LAYER == 1) ? 64 : 32;
    constexpr int AP   = 136;                  // A pitch (halves)
    constexpr int BP   = (LAYER == 1) ? 72 : 40;   // B pitch (halves)
    constexpr int CP   = NOUT + 4;             // C pitch (floats)

    __shared__ __align__(16) char smem[64 * AP * 2 + 128 * BP * 2 + NOUT * 4];
    __half* Ah = (__half*)smem;                          // 64 x AP
    __half* Bh = (__half*)(smem + 64 * AP * 2);          // 128 x BP
    float*  bs = (float*) (smem + 64 * AP * 2 + 128 * BP * 2);
    float*  Cf = (float*)smem;                           // aliases Ah

    int tid  = threadIdx.x;
    int wid  = tid >> 5;
    int blockBase = blockIdx.x * 64;
    const __half* TAB16 = (LAYER == 1) ? g_feat16 : g_h116;

    // ---- stage A: s,p from fp16 f and fp16 g ------------------------------
    for (int idx = tid; idx < 64 * 8; idx += 256) {
        int m  = idx >> 3;
        int q8 = idx & 7;
        int node = blockBase + m;
        uint4 fh = *(const uint4*)(TAB16 + (size_t)node * 64 + q8 * 8);
        uint4 gh = __ldcs((const uint4*)(g_hneigh16 + (size_t)node * 64 + q8 * 8));
        const __half2* f2p = (const __half2*)&fh;
        const __half2* g2p = (const __half2*)&gh;
        uint4 s4, p4;
        __half2* s2 = (__half2*)&s4;
        __half2* p2 = (__half2*)&p4;
        #pragma unroll
        for (int k = 0; k < 4; k++) {
            s2[k] = __hadd2(f2p[k], g2p[k]);
            p2[k] = __hmul2(f2p[k], g2p[k]);
        }
        *(uint4*)(Ah + m * AP + q8 * 8)      = s4;
        *(uint4*)(Ah + m * AP + 64 + q8 * 8) = p4;
    }
    // ---- stage B: [W1;W2] as fp16 -----------------------------------------
    for (int idx = tid; idx < 64 * NOUT; idx += 256) {   // half2 granularity
        int e = idx * 2;
        int k = e / NOUT;
        int j = e % NOUT;
        float2 w = (k < 64) ? *(const float2*)(W1 + k * NOUT + j)
                            : *(const float2*)(W2 + (k - 64) * NOUT + j);
        *(__half2*)(Bh + k * BP + j) = __floats2half2_rn(w.x, w.y);
    }
    if (tid < NOUT) bs[tid] = b1[tid] + b2[tid];
    __syncthreads();

    // ---- wmma mainloop ----------------------------------------------------
    constexpr int NT = NOUT / 16;             // n-tiles: 4 / 2
    constexpr int TPW = (4 * NT) / 8;         // tiles per warp: 2 / 1
    int mt = wid >> 1;
    int n0 = (TPW == 2) ? ((wid & 1) * 2) : (wid & 1);

    wmma::fragment<wmma::accumulator, 16, 16, 16, float> cfrag[TPW];
    #pragma unroll
    for (int t = 0; t < TPW; t++) wmma::fill_fragment(cfrag[t], 0.f);

    #pragma unroll
    for (int ks = 0; ks < 8; ks++) {
        wmma::fragment<wmma::matrix_a, 16, 16, 16, __half, wmma::row_major> afrag;
        wmma::load_matrix_sync(afrag, Ah + mt * 16 * AP + ks * 16, AP);
        #pragma unroll
        for (int t = 0; t < TPW; t++) {
            wmma::fragment<wmma::matrix_b, 16, 16, 16, __half, wmma::row_major> bfrag;
            wmma::load_matrix_sync(bfrag, Bh + ks * 16 * BP + (n0 + t) * 16, BP);
            wmma::mma_sync(cfrag[t], afrag, bfrag, cfrag[t]);
        }
    }
    __syncthreads();   // all reads of Ah done before aliased Cf writes
    #pragma unroll
    for (int t = 0; t < TPW; t++)
        wmma::store_matrix_sync(Cf + mt * 16 * CP + (n0 + t) * 16, cfrag[t], CP, wmma::mem_row_major);
    __syncthreads();

    // ---- epilogue: bias, lrelu, row l2-norm, store ------------------------
    constexpr int CPT = NOUT / 4;             // cols per thread: 16 / 8
    int m  = tid >> 2;
    int qd = tid & 3;
    int c0 = qd * CPT;
    float v[CPT];
    float sq = 0.f;
    #pragma unroll
    for (int j = 0; j < CPT; j++) {
        float s = Cf[m * CP + c0 + j] + bs[c0 + j];
        s = (s >= 0.f) ? s : 0.01f * s;
        v[j] = s;
        sq = fmaf(s, s, sq);
    }
    sq += __shfl_xor_sync(0xffffffffu, sq, 1);
    sq += __shfl_xor_sync(0xffffffffu, sq, 2);
    float inv = 1.f / fmaxf(sqrtf(sq), 1e-12f);
    int node = blockBase + m;
    float* OUT = (LAYER == 1) ? g_h1 : g_h2;
    #pragma unroll
    for (int j = 0; j < CPT; j++) {
        float o = v[j] * inv;
        OUT[(size_t)node * NOUT + c0 + j] = o;
        if (LAYER == 1)
            g_h116[(size_t)node * 64 + c0 + j] = __float2half_rn(o);
    }
}

// ---------------- scoring: one warp per batch element ----------------------
__global__ void __launch_bounds__(256) k_score(const float* __restrict__ uw,
                                               const float* __restrict__ ew,
                                               const int* __restrict__ uid,
                                               const int* __restrict__ pid,
                                               const int* __restrict__ nid,
                                               float* __restrict__ out) {
    int gidx = blockIdx.x * 256 + threadIdx.x;
    int b = gidx >> 5;
    int l = gidx & 31;
    if (b >= BATCH) return;
    int u  = uid[b];
    int pe = pid[b];
    int ne = nid[b];
    int p  = N_USERS + pe;
    int q  = N_USERS + ne;

    const float* fu = uw + (size_t)u * 64;
    const float* fp = ew + (size_t)pe * 64;
    const float* fq = ew + (size_t)ne * 64;

    float sp = 0.f, sn = 0.f;
    #pragma unroll
    for (int r = 0; r < 2; r++) {
        int cidx = l + r * 32;
        float a = fu[cidx];
        sp = fmaf(a, fp[cidx], sp);
        sn = fmaf(a, fq[cidx], sn);
    }
    #pragma unroll
    for (int r = 0; r < 2; r++) {
        int cidx = l + r * 32;
        float a = g_h1[(size_t)u * 64 + cidx];
        sp = fmaf(a, g_h1[(size_t)p * 64 + cidx], sp);
        sn = fmaf(a, g_h1[(size_t)q * 64 + cidx], sn);
    }
    {
        float a = g_h2[(size_t)u * 32 + l];
        sp = fmaf(a, g_h2[(size_t)p * 32 + l], sp);
        sn = fmaf(a, g_h2[(size_t)q * 32 + l], sn);
    }
    #pragma unroll
    for (int o = 16; o > 0; o >>= 1) {
        sp += __shfl_xor_sync(0xffffffffu, sp, o);
        sn += __shfl_xor_sync(0xffffffffu, sn, o);
    }
    if (l == 0) { out[b] = sp; out[BATCH + b] = sn; }
}

// ---------------- launch ---------------------------------------------------
extern "C" void kernel_launch(void* const* d_in, const int* in_sizes, int n_in,
                              void* d_out, int out_size) {
    const float* uw   = (const float*)d_in[0];
    const float* ew   = (const float*)d_in[1];
    const float* W1a  = (const float*)d_in[2];
    const float* b1a  = (const float*)d_in[3];
    const float* W2a  = (const float*)d_in[4];
    const float* b2a  = (const float*)d_in[5];
    const float* W1b  = (const float*)d_in[6];
    const float* b1b  = (const float*)d_in[7];
    const float* W2b  = (const float*)d_in[8];
    const float* b2b  = (const float*)d_in[9];
    const float* values   = (const float*)d_in[10];
    const int*   target   = (const int*)d_in[11];
    const int*   neighbor = (const int*)d_in[12];
    const int*   uid      = (const int*)d_in[13];
    const int*   pid      = (const int*)d_in[14];
    const int*   nid      = (const int*)d_in[15];
    float* out = (float*)d_out;

    // fp16 table (+ count/ticket zeroing) and CSR build
    k_tofp16<<<(N_NODES * 64 / 8) / 256, 256>>>(uw, ew);
    k_count<<<(N_EDGES / 4) / 256, 256>>>(target);
    k_scan1<<<SCAN_BLOCKS, 1024>>>();
    k_scan3<<<SCAN_BLOCKS, 1024>>>();
    k_scatter<<<N_EDGES / 256, 256>>>(target, neighbor, values);

    // Layer 1
    k_gather<1><<<N_NODES / 8, 256>>>();
    k_dense<1><<<N_NODES / 64, 256>>>(W1a, b1a, W2a, b2a);

    // Layer 2
    k_gather<2><<<N_NODES / 8, 256>>>();
    k_dense<2><<<N_NODES / 64, 256>>>(W1b, b1b, W2b, b2b);

    // Scores
    k_score<<<(BATCH * 32) / 256, 256>>>(uw, ew, uid, pid, nid, out);
}

// round 14
// speedup vs baseline: 1.1876x; 1.1876x over previous
#include <cuda_runtime.h>
#include <cuda_fp16.h>
#include <mma.h>
#include <cstdint>

using namespace nvcuda;

#define N_USERS    50000
#define N_ENTITIES 150000
#define N_NODES    200000
#define N_EDGES    3200000
#define BATCH      4096
#define SCAN_BLOCKS 196            // 196*1024 = 200704 >= N_NODES

// ---------------- scratch (device globals; no allocation allowed) ----------
__device__ __align__(16) __half g_hneigh16[(size_t)N_NODES * 64]; // fp16 neighbor sums
__device__ __align__(16) __half g_feat16[(size_t)N_NODES * 64];   // fp16 ego features
__device__ __align__(16) __half g_h116[(size_t)N_NODES * 64];     // fp16 h1
__device__ __align__(16) __half g_h216[(size_t)N_NODES * 32];     // fp16 h2
__device__ __align__(16) int    g_count[N_NODES];
__device__ __align__(16) int    g_rowstart[N_NODES + 4];
__device__ __align__(16) int    g_cursor[N_NODES + 4];
__device__ __align__(16) int    g_bsum[SCAN_BLOCKS];
__device__ __align__(16) int    g_boff[SCAN_BLOCKS];
__device__ int                  g_ticket;
__device__ __align__(16) int2   g_srt[N_EDGES];     // {neighbor, value-bits} sorted by target

__device__ __forceinline__ const float* feat0_row(const float* uw, const float* ew, int n) {
    return (n < N_USERS) ? (uw + (size_t)n * 64) : (ew + (size_t)(n - N_USERS) * 64);
}

// ---------------- fp16 feature table build (+ zero counts, ticket) ---------
__global__ void __launch_bounds__(256) k_tofp16(const float* __restrict__ uw,
                                                const float* __restrict__ ew) {
    size_t i = (size_t)blockIdx.x * 256 + threadIdx.x;
    if (i < N_NODES / 4) ((int4*)g_count)[i] = make_int4(0, 0, 0, 0);
    if (i == 0) g_ticket = 0;
    size_t base = i * 8;
    int node = (int)(base >> 6);
    int col  = (int)(base & 63);
    const float* row = feat0_row(uw, ew, node);
    float4 a = *(const float4*)(row + col);
    float4 b = *(const float4*)(row + col + 4);
    __half2 h0 = __floats2half2_rn(a.x, a.y);
    __half2 h1 = __floats2half2_rn(a.z, a.w);
    __half2 h2 = __floats2half2_rn(b.x, b.y);
    __half2 h3 = __floats2half2_rn(b.z, b.w);
    uint4 out;
    out.x = *(const unsigned*)&h0;
    out.y = *(const unsigned*)&h1;
    out.z = *(const unsigned*)&h2;
    out.w = *(const unsigned*)&h3;
    *(uint4*)(g_feat16 + base) = out;
}

// ---------------- CSR build ------------------------------------------------
__global__ void __launch_bounds__(256) k_count(const int* __restrict__ target) {
    int e4 = blockIdx.x * 256 + threadIdx.x;          // grid exact: 800000/256
    int4 t = __ldcs((const int4*)target + e4);
    atomicAdd(&g_count[t.x], 1);
    atomicAdd(&g_count[t.y], 1);
    atomicAdd(&g_count[t.z], 1);
    atomicAdd(&g_count[t.w], 1);
}

// Phase 1: per-block exclusive scan of 1024 counts; last block also scans
// the 196 block totals into g_boff (ticket pattern).
__global__ void __launch_bounds__(1024) k_scan1() {
    __shared__ int warp_tot[32];
    __shared__ int isLast;
    int i = blockIdx.x * 1024 + threadIdx.x;
    int lane = threadIdx.x & 31, w = threadIdx.x >> 5;
    int v = (i < N_NODES) ? g_count[i] : 0;
    int x = v;
    #pragma unroll
    for (int o = 1; o < 32; o <<= 1) {
        int y = __shfl_up_sync(0xffffffffu, x, o);
        if (lane >= o) x += y;
    }
    if (lane == 31) warp_tot[w] = x;
    if (threadIdx.x == 0) isLast = 0;
    __syncthreads();
    if (w == 0) {
        int t = warp_tot[lane];
        #pragma unroll
        for (int o = 1; o < 32; o <<= 1) {
            int y = __shfl_up_sync(0xffffffffu, t, o);
            if (lane >= o) t += y;
        }
        warp_tot[lane] = t;
    }
    __syncthreads();
    int excl = x - v + ((w > 0) ? warp_tot[w - 1] : 0);
    if (i < N_NODES) g_rowstart[i] = excl;
    if (threadIdx.x == 1023) {
        g_bsum[blockIdx.x] = excl + v;
        __threadfence();
        int tkt = atomicAdd(&g_ticket, 1);
        if (tkt == SCAN_BLOCKS - 1) isLast = 1;
    }
    __syncthreads();
    if (isLast) {                                     // uniform per block
        int t = threadIdx.x;
        int val = (t < SCAN_BLOCKS) ? __ldcg(&g_bsum[t]) : 0;
        int x2 = val;
        #pragma unroll
        for (int o = 1; o < 32; o <<= 1) {
            int y = __shfl_up_sync(0xffffffffu, x2, o);
            if (lane >= o) x2 += y;
        }
        if (lane == 31) warp_tot[w] = x2;
        __syncthreads();
        if (t < SCAN_BLOCKS) {
            int off = 0;
            for (int k = 0; k < w; k++) off += warp_tot[k];
            g_boff[t] = x2 - val + off;
        }
    }
}

// Phase 3: add block offsets.
__global__ void __launch_bounds__(1024) k_scan3() {
    int i = blockIdx.x * 1024 + threadIdx.x;
    if (i < N_NODES) {
        int v = g_rowstart[i] + g_boff[blockIdx.x];
        g_rowstart[i] = v;
        g_cursor[i]   = v;
    }
    if (i == 0) g_rowstart[N_NODES] = N_EDGES;
}

// Scatter, 4 edges/thread: int4 loads, 4 independent atomics in flight.
__global__ void __launch_bounds__(256) k_scatter(const int* __restrict__ target,
                                                const int* __restrict__ neighbor,
                                                const float* __restrict__ values) {
    int e4 = blockIdx.x * 256 + threadIdx.x;          // grid exact: 800000/256
    int4 t = __ldcs((const int4*)target + e4);
    int4 nb = __ldcs((const int4*)neighbor + e4);
    float4 v = __ldcs((const float4*)values + e4);
    int p0 = atomicAdd(&g_cursor[t.x], 1);
    int p1 = atomicAdd(&g_cursor[t.y], 1);
    int p2 = atomicAdd(&g_cursor[t.z], 1);
    int p3 = atomicAdd(&g_cursor[t.w], 1);
    __stcs(&g_srt[p0], make_int2(nb.x, __float_as_int(v.x)));
    __stcs(&g_srt[p1], make_int2(nb.y, __float_as_int(v.y)));
    __stcs(&g_srt[p2], make_int2(nb.z, __float_as_int(v.z)));
    __stcs(&g_srt[p3], make_int2(nb.w, __float_as_int(v.w)));
}

// ---------------- CSR gather (fp16 rows, pipelined records) ----------------
// One warp per node: 16 lanes x uint2 cover the 128B fp16 row, the two
// halves take alternate edges. Next record prefetched before the current
// feature row is consumed. Accumulate fp32, store fp16.  (FROZEN: R12 form.)
template <int LAYER>
__global__ void __launch_bounds__(256) k_gather() {
    int n = (blockIdx.x * 256 + threadIdx.x) >> 5;    // grid exact: 25000*8 warps
    int lane = threadIdx.x & 31;
    int c = lane & 15, half = lane >> 4;
    const __half* TAB = (LAYER == 1) ? g_feat16 : g_h116;
    int base = g_rowstart[n];
    int end  = g_rowstart[n + 1];
    float4 acc = make_float4(0.f, 0.f, 0.f, 0.f);
    int i = base + half;
    int2 e = (i < end) ? __ldcs(&g_srt[i]) : make_int2(0, 0);
    for (; i < end; i += 2) {
        int2 cure = e;
        if (i + 2 < end) e = __ldcs(&g_srt[i + 2]);   // prefetch next record
        float v = __int_as_float(cure.y);
        uint2 hv = *(const uint2*)(TAB + (size_t)cure.x * 64 + c * 4);
        float2 f01 = __half22float2(*(const __half2*)&hv.x);
        float2 f23 = __half22float2(*(const __half2*)&hv.y);
        acc.x = fmaf(f01.x, v, acc.x);
        acc.y = fmaf(f01.y, v, acc.y);
        acc.z = fmaf(f23.x, v, acc.z);
        acc.w = fmaf(f23.y, v, acc.w);
    }
    acc.x += __shfl_xor_sync(0xffffffffu, acc.x, 16);
    acc.y += __shfl_xor_sync(0xffffffffu, acc.y, 16);
    acc.z += __shfl_xor_sync(0xffffffffu, acc.z, 16);
    acc.w += __shfl_xor_sync(0xffffffffu, acc.w, 16);
    if (half == 0) {
        __half2 a01 = __floats2half2_rn(acc.x, acc.y);
        __half2 a23 = __floats2half2_rn(acc.z, acc.w);
        int2 st = make_int2(*(const int*)&a01, *(const int*)&a23);
        __stcs((int2*)(g_hneigh16 + (size_t)n * 64 + c * 4), st);
    }
}

// ---------------- dense layers via wmma (fp16 x fp16 -> fp32) --------------
// f and g both fp16; s/p via __hadd2/__hmul2. Outputs fp16 only.
template <int LAYER>
__global__ void __launch_bounds__(256) k_dense(const float* __restrict__ W1,
                                               const float* __restrict__ b1,
                                               const float* __restrict__ W2,
                                               const float* __restrict__ b2) {
    constexpr int NOUT = (LAYER == 1) ? 64 : 32;
    constexpr int AP   = 136;                  // A pitch (halves)
    constexpr int BP   = (LAYER == 1) ? 72 : 40;   // B pitch (halves)
    constexpr int CP   = NOUT + 4;             // C pitch (floats)

    __shared__ __align__(16) char smem[64 * AP * 2 + 128 * BP * 2 + NOUT * 4];
    __half* Ah = (__half*)smem;                          // 64 x AP
    __half* Bh = (__half*)(smem + 64 * AP * 2);          // 128 x BP
    float*  bs = (float*) (smem + 64 * AP * 2 + 128 * BP * 2);
    float*  Cf = (float*)smem;                           // aliases Ah

    int tid  = threadIdx.x;
    int wid  = tid >> 5;
    int blockBase = blockIdx.x * 64;
    const __half* TAB16 = (LAYER == 1) ? g_feat16 : g_h116;

    // ---- stage A: s,p from fp16 f and fp16 g ------------------------------
    for (int idx = tid; idx < 64 * 8; idx += 256) {
        int m  = idx >> 3;
        int q8 = idx & 7;
        int node = blockBase + m;
        uint4 fh = *(const uint4*)(TAB16 + (size_t)node * 64 + q8 * 8);
        uint4 gh = __ldcs((const uint4*)(g_hneigh16 + (size_t)node * 64 + q8 * 8));
        const __half2* f2p = (const __half2*)&fh;
        const __half2* g2p = (const __half2*)&gh;
        uint4 s4, p4;
        __half2* s2 = (__half2*)&s4;
        __half2* p2 = (__half2*)&p4;
        #pragma unroll
        for (int k = 0; k < 4; k++) {
            s2[k] = __hadd2(f2p[k], g2p[k]);
            p2[k] = __hmul2(f2p[k], g2p[k]);
        }
        *(uint4*)(Ah + m * AP + q8 * 8)      = s4;
        *(uint4*)(Ah + m * AP + 64 + q8 * 8) = p4;
    }
    // ---- stage B: [W1;W2] as fp16 -----------------------------------------
    for (int idx = tid; idx < 64 * NOUT; idx += 256) {   // half2 granularity
        int e = idx * 2;
        int k = e / NOUT;
        int j = e % NOUT;
        float2 w = (k < 64) ? *(const float2*)(W1 + k * NOUT + j)
                            : *(const float2*)(W2 + (k - 64) * NOUT + j);
        *(__half2*)(Bh + k * BP + j) = __floats2half2_rn(w.x, w.y);
    }
    if (tid < NOUT) bs[tid] = b1[tid] + b2[tid];
    __syncthreads();

    // ---- wmma mainloop ----------------------------------------------------
    constexpr int NT = NOUT / 16;             // n-tiles: 4 / 2
    constexpr int TPW = (4 * NT) / 8;         // tiles per warp: 2 / 1
    int mt = wid >> 1;
    int n0 = (TPW == 2) ? ((wid & 1) * 2) : (wid & 1);

    wmma::fragment<wmma::accumulator, 16, 16, 16, float> cfrag[TPW];
    #pragma unroll
    for (int t = 0; t < TPW; t++) wmma::fill_fragment(cfrag[t], 0.f);

    #pragma unroll
    for (int ks = 0; ks < 8; ks++) {
        wmma::fragment<wmma::matrix_a, 16, 16, 16, __half, wmma::row_major> afrag;
        wmma::load_matrix_sync(afrag, Ah + mt * 16 * AP + ks * 16, AP);
        #pragma unroll
        for (int t = 0; t < TPW; t++) {
            wmma::fragment<wmma::matrix_b, 16, 16, 16, __half, wmma::row_major> bfrag;
            wmma::load_matrix_sync(bfrag, Bh + ks * 16 * BP + (n0 + t) * 16, BP);
            wmma::mma_sync(cfrag[t], afrag, bfrag, cfrag[t]);
        }
    }
    __syncthreads();   // all reads of Ah done before aliased Cf writes
    #pragma unroll
    for (int t = 0; t < TPW; t++)
        wmma::store_matrix_sync(Cf + mt * 16 * CP + (n0 + t) * 16, cfrag[t], CP, wmma::mem_row_major);
    __syncthreads();

    // ---- epilogue: bias, lrelu, row l2-norm, fp16 store -------------------
    constexpr int CPT = NOUT / 4;             // cols per thread: 16 / 8
    int m  = tid >> 2;
    int qd = tid & 3;
    int c0 = qd * CPT;
    float v[CPT];
    float sq = 0.f;
    #pragma unroll
    for (int j = 0; j < CPT; j++) {
        float s = Cf[m * CP + c0 + j] + bs[c0 + j];
        s = (s >= 0.f) ? s : 0.01f * s;
        v[j] = s;
        sq = fmaf(s, s, sq);
    }
    sq += __shfl_xor_sync(0xffffffffu, sq, 1);
    sq += __shfl_xor_sync(0xffffffffu, sq, 2);
    float inv = 1.f / fmaxf(sqrtf(sq), 1e-12f);
    int node = blockBase + m;
    __half* OUT = (LAYER == 1) ? g_h116 : g_h216;
    #pragma unroll
    for (int j = 0; j < CPT; j += 2) {
        __half2 h = __floats2half2_rn(v[j] * inv, v[j + 1] * inv);
        *(__half2*)(OUT + (size_t)node * NOUT + c0 + j) = h;
    }
}

// ---------------- scoring: one warp per batch element (fp16 h1/h2) ---------
__global__ void __launch_bounds__(256) k_score(const float* __restrict__ uw,
                                               const float* __restrict__ ew,
                                               const int* __restrict__ uid,
                                               const int* __restrict__ pid,
                                               const int* __restrict__ nid,
                                               float* __restrict__ out) {
    int gidx = blockIdx.x * 256 + threadIdx.x;
    int b = gidx >> 5;
    int l = gidx & 31;
    if (b >= BATCH) return;
    int u  = uid[b];
    int pe = pid[b];
    int ne = nid[b];
    int p  = N_USERS + pe;
    int q  = N_USERS + ne;

    const float* fu = uw + (size_t)u * 64;
    const float* fp = ew + (size_t)pe * 64;
    const float* fq = ew + (size_t)ne * 64;

    float sp = 0.f, sn = 0.f;
    // dims 0..63 : ego embedding (fp32 inputs)
    #pragma unroll
    for (int r = 0; r < 2; r++) {
        int cidx = l + r * 32;
        float a = fu[cidx];
        sp = fmaf(a, fp[cidx], sp);
        sn = fmaf(a, fq[cidx], sn);
    }
    // dims 64..127 : h1 (fp16, 2 halves per lane)
    {
        __half2 au = *(const __half2*)(g_h116 + (size_t)u * 64 + l * 2);
        __half2 ap = *(const __half2*)(g_h116 + (size_t)p * 64 + l * 2);
        __half2 aq = *(const __half2*)(g_h116 + (size_t)q * 64 + l * 2);
        float2 fa = __half22float2(au);
        float2 fb = __half22float2(ap);
        float2 fc = __half22float2(aq);
        sp = fmaf(fa.x, fb.x, sp); sp = fmaf(fa.y, fb.y, sp);
        sn = fmaf(fa.x, fc.x, sn); sn = fmaf(fa.y, fc.y, sn);
    }
    // dims 128..159 : h2 (fp16, 1 half per lane)
    {
        float a = __half2float(g_h216[(size_t)u * 32 + l]);
        float bpv = __half2float(g_h216[(size_t)p * 32 + l]);
        float bnv = __half2float(g_h216[(size_t)q * 32 + l]);
        sp = fmaf(a, bpv, sp);
        sn = fmaf(a, bnv, sn);
    }
    #pragma unroll
    for (int o = 16; o > 0; o >>= 1) {
        sp += __shfl_xor_sync(0xffffffffu, sp, o);
        sn += __shfl_xor_sync(0xffffffffu, sn, o);
    }
    if (l == 0) { out[b] = sp; out[BATCH + b] = sn; }
}

// ---------------- launch ---------------------------------------------------
extern "C" void kernel_launch(void* const* d_in, const int* in_sizes, int n_in,
                              void* d_out, int out_size) {
    const float* uw   = (const float*)d_in[0];
    const float* ew   = (const float*)d_in[1];
    const float* W1a  = (const float*)d_in[2];
    const float* b1a  = (const float*)d_in[3];
    const float* W2a  = (const float*)d_in[4];
    const float* b2a  = (const float*)d_in[5];
    const float* W1b  = (const float*)d_in[6];
    const float* b1b  = (const float*)d_in[7];
    const float* W2b  = (const float*)d_in[8];
    const float* b2b  = (const float*)d_in[9];
    const float* values   = (const float*)d_in[10];
    const int*   target   = (const int*)d_in[11];
    const int*   neighbor = (const int*)d_in[12];
    const int*   uid      = (const int*)d_in[13];
    const int*   pid      = (const int*)d_in[14];
    const int*   nid      = (const int*)d_in[15];
    float* out = (float*)d_out;

    // fp16 table (+ count/ticket zeroing) and CSR build
    k_tofp16<<<(N_NODES * 64 / 8) / 256, 256>>>(uw, ew);
    k_count<<<(N_EDGES / 4) / 256, 256>>>(target);
    k_scan1<<<SCAN_BLOCKS, 1024>>>();
    k_scan3<<<SCAN_BLOCKS, 1024>>>();
    k_scatter<<<(N_EDGES / 4) / 256, 256>>>(target, neighbor, values);

    // Layer 1
    k_gather<1><<<N_NODES / 8, 256>>>();
    k_dense<1><<<N_NODES / 64, 256>>>(W1a, b1a, W2a, b2a);

    // Layer 2
    k_gather<2><<<N_NODES / 8, 256>>>();
    k_dense<2><<<N_NODES / 64, 256>>>(W1b, b1b, W2b, b2b);

    // Scores
    k_score<<<(BATCH * 32) / 256, 256>>>(uw, ew, uid, pid, nid, out);
}

// round 15
// speedup vs baseline: 1.2071x; 1.0164x over previous
#include <cuda_runtime.h>
#include <cuda_fp16.h>
#include <mma.h>
#include <cstdint>

using namespace nvcuda;

#define N_USERS    50000
#define N_ENTITIES 150000
#define N_NODES    200000
#define N_EDGES    3200000
#define BATCH      4096
#define SCAN_BLOCKS 196            // 196*1024 = 200704 >= N_NODES

// ---------------- scratch (device globals; no allocation allowed) ----------
__device__ __align__(16) __half g_hneigh16[(size_t)N_NODES * 64]; // fp16 neighbor sums
__device__ __align__(16) __half g_feat16[(size_t)N_NODES * 64];   // fp16 ego features
__device__ __align__(16) __half g_h116[(size_t)N_NODES * 64];     // fp16 h1
__device__ __align__(16) __half g_h216[(size_t)N_NODES * 32];     // fp16 h2
__device__ __align__(16) int    g_count[N_NODES];
__device__ __align__(16) int    g_rowstart[N_NODES + 4];
__device__ __align__(16) int    g_cursor[N_NODES + 4];
__device__ __align__(16) int    g_bsum[SCAN_BLOCKS];
__device__ __align__(16) int    g_boff[SCAN_BLOCKS];
__device__ int                  g_ticket;
__device__ __align__(16) unsigned g_srt[N_EDGES];   // packed {nb<<14 | v_q14}, sorted

__device__ __forceinline__ const float* feat0_row(const float* uw, const float* ew, int n) {
    return (n < N_USERS) ? (uw + (size_t)n * 64) : (ew + (size_t)(n - N_USERS) * 64);
}

// ---------------- fp16 feature table build (+ zero counts, ticket) ---------
__global__ void __launch_bounds__(256) k_tofp16(const float* __restrict__ uw,
                                                const float* __restrict__ ew) {
    size_t i = (size_t)blockIdx.x * 256 + threadIdx.x;
    if (i < N_NODES / 4) ((int4*)g_count)[i] = make_int4(0, 0, 0, 0);
    if (i == 0) g_ticket = 0;
    size_t base = i * 8;
    int node = (int)(base >> 6);
    int col  = (int)(base & 63);
    const float* row = feat0_row(uw, ew, node);
    float4 a = *(const float4*)(row + col);
    float4 b = *(const float4*)(row + col + 4);
    __half2 h0 = __floats2half2_rn(a.x, a.y);
    __half2 h1 = __floats2half2_rn(a.z, a.w);
    __half2 h2 = __floats2half2_rn(b.x, b.y);
    __half2 h3 = __floats2half2_rn(b.z, b.w);
    uint4 out;
    out.x = *(const unsigned*)&h0;
    out.y = *(const unsigned*)&h1;
    out.z = *(const unsigned*)&h2;
    out.w = *(const unsigned*)&h3;
    *(uint4*)(g_feat16 + base) = out;
}

// ---------------- CSR build ------------------------------------------------
__global__ void __launch_bounds__(256) k_count(const int* __restrict__ target) {
    int e4 = blockIdx.x * 256 + threadIdx.x;          // grid exact: 800000/256
    int4 t = __ldcs((const int4*)target + e4);
    atomicAdd(&g_count[t.x], 1);
    atomicAdd(&g_count[t.y], 1);
    atomicAdd(&g_count[t.z], 1);
    atomicAdd(&g_count[t.w], 1);
}

// Phase 1: per-block exclusive scan of 1024 counts; last block also scans
// the 196 block totals into g_boff (ticket pattern).
__global__ void __launch_bounds__(1024) k_scan1() {
    __shared__ int warp_tot[32];
    __shared__ int isLast;
    int i = blockIdx.x * 1024 + threadIdx.x;
    int lane = threadIdx.x & 31, w = threadIdx.x >> 5;
    int v = (i < N_NODES) ? g_count[i] : 0;
    int x = v;
    #pragma unroll
    for (int o = 1; o < 32; o <<= 1) {
        int y = __shfl_up_sync(0xffffffffu, x, o);
        if (lane >= o) x += y;
    }
    if (lane == 31) warp_tot[w] = x;
    if (threadIdx.x == 0) isLast = 0;
    __syncthreads();
    if (w == 0) {
        int t = warp_tot[lane];
        #pragma unroll
        for (int o = 1; o < 32; o <<= 1) {
            int y = __shfl_up_sync(0xffffffffu, t, o);
            if (lane >= o) t += y;
        }
        warp_tot[lane] = t;
    }
    __syncthreads();
    int excl = x - v + ((w > 0) ? warp_tot[w - 1] : 0);
    if (i < N_NODES) g_rowstart[i] = excl;
    if (threadIdx.x == 1023) {
        g_bsum[blockIdx.x] = excl + v;
        __threadfence();
        int tkt = atomicAdd(&g_ticket, 1);
        if (tkt == SCAN_BLOCKS - 1) isLast = 1;
    }
    __syncthreads();
    if (isLast) {                                     // uniform per block
        int t = threadIdx.x;
        int val = (t < SCAN_BLOCKS) ? __ldcg(&g_bsum[t]) : 0;
        int x2 = val;
        #pragma unroll
        for (int o = 1; o < 32; o <<= 1) {
            int y = __shfl_up_sync(0xffffffffu, x2, o);
            if (lane >= o) x2 += y;
        }
        if (lane == 31) warp_tot[w] = x2;
        __syncthreads();
        if (t < SCAN_BLOCKS) {
            int off = 0;
            for (int k = 0; k < w; k++) off += warp_tot[k];
            g_boff[t] = x2 - val + off;
        }
    }
}

// Phase 3: add block offsets.
__global__ void __launch_bounds__(1024) k_scan3() {
    int i = blockIdx.x * 1024 + threadIdx.x;
    if (i < N_NODES) {
        int v = g_rowstart[i] + g_boff[blockIdx.x];
        g_rowstart[i] = v;
        g_cursor[i]   = v;
    }
    if (i == 0) g_rowstart[N_NODES] = N_EDGES;
}

// Scatter, 4 edges/thread: int4 loads, 4 independent atomics, 4B packed recs.
__global__ void __launch_bounds__(256) k_scatter(const int* __restrict__ target,
                                                const int* __restrict__ neighbor,
                                                const float* __restrict__ values) {
    int e4 = blockIdx.x * 256 + threadIdx.x;          // grid exact: 800000/256
    int4 t = __ldcs((const int4*)target + e4);
    int4 nb = __ldcs((const int4*)neighbor + e4);
    float4 v = __ldcs((const float4*)values + e4);
    unsigned r0 = ((unsigned)nb.x << 14) | (unsigned)min(16383, __float2int_rd(v.x * 16384.f));
    unsigned r1 = ((unsigned)nb.y << 14) | (unsigned)min(16383, __float2int_rd(v.y * 16384.f));
    unsigned r2 = ((unsigned)nb.z << 14) | (unsigned)min(16383, __float2int_rd(v.z * 16384.f));
    unsigned r3 = ((unsigned)nb.w << 14) | (unsigned)min(16383, __float2int_rd(v.w * 16384.f));
    int p0 = atomicAdd(&g_cursor[t.x], 1);
    int p1 = atomicAdd(&g_cursor[t.y], 1);
    int p2 = atomicAdd(&g_cursor[t.z], 1);
    int p3 = atomicAdd(&g_cursor[t.w], 1);
    __stcs(&g_srt[p0], r0);
    __stcs(&g_srt[p1], r1);
    __stcs(&g_srt[p2], r2);
    __stcs(&g_srt[p3], r3);
}

// ---------------- CSR gather (fp16 rows, pipelined packed records) ---------
// One warp per node: 16 lanes x uint2 cover the 128B fp16 row, the two
// halves take alternate edges (adjacent 4B records -> merged wavefront).
// Next record prefetched before the current feature row is consumed.
// Accumulate fp32, store fp16.  (Structure FROZEN: R12 form.)
template <int LAYER>
__global__ void __launch_bounds__(256) k_gather() {
    int n = (blockIdx.x * 256 + threadIdx.x) >> 5;    // grid exact: 25000*8 warps
    int lane = threadIdx.x & 31;
    int c = lane & 15, half = lane >> 4;
    const __half* TAB = (LAYER == 1) ? g_feat16 : g_h116;
    int base = g_rowstart[n];
    int end  = g_rowstart[n + 1];
    float4 acc = make_float4(0.f, 0.f, 0.f, 0.f);
    int i = base + half;
    unsigned e = (i < end) ? __ldcs(&g_srt[i]) : 0u;
    for (; i < end; i += 2) {
        unsigned cure = e;
        if (i + 2 < end) e = __ldcs(&g_srt[i + 2]);   // prefetch next record
        float v = (float)(cure & 16383u) * (1.0f / 16384.0f);
        int nb = (int)(cure >> 14);
        uint2 hv = *(const uint2*)(TAB + (size_t)nb * 64 + c * 4);
        float2 f01 = __half22float2(*(const __half2*)&hv.x);
        float2 f23 = __half22float2(*(const __half2*)&hv.y);
        acc.x = fmaf(f01.x, v, acc.x);
        acc.y = fmaf(f01.y, v, acc.y);
        acc.z = fmaf(f23.x, v, acc.z);
        acc.w = fmaf(f23.y, v, acc.w);
    }
    acc.x += __shfl_xor_sync(0xffffffffu, acc.x, 16);
    acc.y += __shfl_xor_sync(0xffffffffu, acc.y, 16);
    acc.z += __shfl_xor_sync(0xffffffffu, acc.z, 16);
    acc.w += __shfl_xor_sync(0xffffffffu, acc.w, 16);
    if (half == 0) {
        __half2 a01 = __floats2half2_rn(acc.x, acc.y);
        __half2 a23 = __floats2half2_rn(acc.z, acc.w);
        int2 st = make_int2(*(const int*)&a01, *(const int*)&a23);
        __stcs((int2*)(g_hneigh16 + (size_t)n * 64 + c * 4), st);
    }
}

// ---------------- dense layers via wmma (fp16 x fp16 -> fp32) --------------
// f and g both fp16; s/p via __hadd2/__hmul2. Outputs fp16 only.
template <int LAYER>
__global__ void __launch_bounds__(256) k_dense(const float* __restrict__ W1,
                                               const float* __restrict__ b1,
                                               const float* __restrict__ W2,
                                               const float* __restrict__ b2) {
    constexpr int NOUT = (LAYER == 1) ? 64 : 32;
    constexpr int AP   = 136;                  // A pitch (halves)
    constexpr int BP   = (LAYER == 1) ? 72 : 40;   // B pitch (halves)
    constexpr int CP   = NOUT + 4;             // C pitch (floats)

    __shared__ __align__(16) char smem[64 * AP * 2 + 128 * BP * 2 + NOUT * 4];
    __half* Ah = (__half*)smem;                          // 64 x AP
    __half* Bh = (__half*)(smem + 64 * AP * 2);          // 128 x BP
    float*  bs = (float*) (smem + 64 * AP * 2 + 128 * BP * 2);
    float*  Cf = (float*)smem;                           // aliases Ah

    int tid  = threadIdx.x;
    int wid  = tid >> 5;
    int blockBase = blockIdx.x * 64;
    const __half* TAB16 = (LAYER == 1) ? g_feat16 : g_h116;

    // ---- stage A: s,p from fp16 f and fp16 g ------------------------------
    for (int idx = tid; idx < 64 * 8; idx += 256) {
        int m  = idx >> 3;
        int q8 = idx & 7;
        int node = blockBase + m;
        uint4 fh = *(const uint4*)(TAB16 + (size_t)node * 64 + q8 * 8);
        uint4 gh = __ldcs((const uint4*)(g_hneigh16 + (size_t)node * 64 + q8 * 8));
        const __half2* f2p = (const __half2*)&fh;
        const __half2* g2p = (const __half2*)&gh;
        uint4 s4, p4;
        __half2* s2 = (__half2*)&s4;
        __half2* p2 = (__half2*)&p4;
        #pragma unroll
        for (int k = 0; k < 4; k++) {
            s2[k] = __hadd2(f2p[k], g2p[k]);
            p2[k] = __hmul2(f2p[k], g2p[k]);
        }
        *(uint4*)(Ah + m * AP + q8 * 8)      = s4;
        *(uint4*)(Ah + m * AP + 64 + q8 * 8) = p4;
    }
    // ---- stage B: [W1;W2] as fp16 -----------------------------------------
    for (int idx = tid; idx < 64 * NOUT; idx += 256) {   // half2 granularity
        int e = idx * 2;
        int k = e / NOUT;
        int j = e % NOUT;
        float2 w = (k < 64) ? *(const float2*)(W1 + k * NOUT + j)
                            : *(const float2*)(W2 + (k - 64) * NOUT + j);
        *(__half2*)(Bh + k * BP + j) = __floats2half2_rn(w.x, w.y);
    }
    if (tid < NOUT) bs[tid] = b1[tid] + b2[tid];
    __syncthreads();

    // ---- wmma mainloop ----------------------------------------------------
    constexpr int NT = NOUT / 16;             // n-tiles: 4 / 2
    constexpr int TPW = (4 * NT) / 8;         // tiles per warp: 2 / 1
    int mt = wid >> 1;
    int n0 = (TPW == 2) ? ((wid & 1) * 2) : (wid & 1);

    wmma::fragment<wmma::accumulator, 16, 16, 16, float> cfrag[TPW];
    #pragma unroll
    for (int t = 0; t < TPW; t++) wmma::fill_fragment(cfrag[t], 0.f);

    #pragma unroll
    for (int ks = 0; ks < 8; ks++) {
        wmma::fragment<wmma::matrix_a, 16, 16, 16, __half, wmma::row_major> afrag;
        wmma::load_matrix_sync(afrag, Ah + mt * 16 * AP + ks * 16, AP);
        #pragma unroll
        for (int t = 0; t < TPW; t++) {
            wmma::fragment<wmma::matrix_b, 16, 16, 16, __half, wmma::row_major> bfrag;
            wmma::load_matrix_sync(bfrag, Bh + ks * 16 * BP + (n0 + t) * 16, BP);
            wmma::mma_sync(cfrag[t], afrag, bfrag, cfrag[t]);
        }
    }
    __syncthreads();   // all reads of Ah done before aliased Cf writes
    #pragma unroll
    for (int t = 0; t < TPW; t++)
        wmma::store_matrix_sync(Cf + mt * 16 * CP + (n0 + t) * 16, cfrag[t], CP, wmma::mem_row_major);
    __syncthreads();

    // ---- epilogue: bias, lrelu, row l2-norm, fp16 store -------------------
    constexpr int CPT = NOUT / 4;             // cols per thread: 16 / 8
    int m  = tid >> 2;
    int qd = tid & 3;
    int c0 = qd * CPT;
    float v[CPT];
    float sq = 0.f;
    #pragma unroll
    for (int j = 0; j < CPT; j++) {
        float s = Cf[m * CP + c0 + j] + bs[c0 + j];
        s = (s >= 0.f) ? s : 0.01f * s;
        v[j] = s;
        sq = fmaf(s, s, sq);
    }
    sq += __shfl_xor_sync(0xffffffffu, sq, 1);
    sq += __shfl_xor_sync(0xffffffffu, sq, 2);
    float inv = 1.f / fmaxf(sqrtf(sq), 1e-12f);
    int node = blockBase + m;
    __half* OUT = (LAYER == 1) ? g_h116 : g_h216;
    #pragma unroll
    for (int j = 0; j < CPT; j += 2) {
        __half2 h = __floats2half2_rn(v[j] * inv, v[j + 1] * inv);
        *(__half2*)(OUT + (size_t)node * NOUT + c0 + j) = h;
    }
}

// ---------------- scoring: one warp per batch element (fp16 h1/h2) ---------
__global__ void __launch_bounds__(256) k_score(const float* __restrict__ uw,
                                               const float* __restrict__ ew,
                                               const int* __restrict__ uid,
                                               const int* __restrict__ pid,
                                               const int* __restrict__ nid,
                                               float* __restrict__ out) {
    int gidx = blockIdx.x * 256 + threadIdx.x;
    int b = gidx >> 5;
    int l = gidx & 31;
    if (b >= BATCH) return;
    int u  = uid[b];
    int pe = pid[b];
    int ne = nid[b];
    int p  = N_USERS + pe;
    int q  = N_USERS + ne;

    const float* fu = uw + (size_t)u * 64;
    const float* fp = ew + (size_t)pe * 64;
    const float* fq = ew + (size_t)ne * 64;

    float sp = 0.f, sn = 0.f;
    // dims 0..63 : ego embedding (fp32 inputs)
    #pragma unroll
    for (int r = 0; r < 2; r++) {
        int cidx = l + r * 32;
        float a = fu[cidx];
        sp = fmaf(a, fp[cidx], sp);
        sn = fmaf(a, fq[cidx], sn);
    }
    // dims 64..127 : h1 (fp16, 2 halves per lane)
    {
        __half2 au = *(const __half2*)(g_h116 + (size_t)u * 64 + l * 2);
        __half2 ap = *(const __half2*)(g_h116 + (size_t)p * 64 + l * 2);
        __half2 aq = *(const __half2*)(g_h116 + (size_t)q * 64 + l * 2);
        float2 fa = __half22float2(au);
        float2 fb = __half22float2(ap);
        float2 fc = __half22float2(aq);
        sp = fmaf(fa.x, fb.x, sp); sp = fmaf(fa.y, fb.y, sp);
        sn = fmaf(fa.x, fc.x, sn); sn = fmaf(fa.y, fc.y, sn);
    }
    // dims 128..159 : h2 (fp16, 1 half per lane)
    {
        float a = __half2float(g_h216[(size_t)u * 32 + l]);
        float bpv = __half2float(g_h216[(size_t)p * 32 + l]);
        float bnv = __half2float(g_h216[(size_t)q * 32 + l]);
        sp = fmaf(a, bpv, sp);
        sn = fmaf(a, bnv, sn);
    }
    #pragma unroll
    for (int o = 16; o > 0; o >>= 1) {
        sp += __shfl_xor_sync(0xffffffffu, sp, o);
        sn += __shfl_xor_sync(0xffffffffu, sn, o);
    }
    if (l == 0) { out[b] = sp; out[BATCH + b] = sn; }
}

// ---------------- launch ---------------------------------------------------
extern "C" void kernel_launch(void* const* d_in, const int* in_sizes, int n_in,
                              void* d_out, int out_size) {
    const float* uw   = (const float*)d_in[0];
    const float* ew   = (const float*)d_in[1];
    const float* W1a  = (const float*)d_in[2];
    const float* b1a  = (const float*)d_in[3];
    const float* W2a  = (const float*)d_in[4];
    const float* b2a  = (const float*)d_in[5];
    const float* W1b  = (const float*)d_in[6];
    const float* b1b  = (const float*)d_in[7];
    const float* W2b  = (const float*)d_in[8];
    const float* b2b  = (const float*)d_in[9];
    const float* values   = (const float*)d_in[10];
    const int*   target   = (const int*)d_in[11];
    const int*   neighbor = (const int*)d_in[12];
    const int*   uid      = (const int*)d_in[13];
    const int*   pid      = (const int*)d_in[14];
    const int*   nid      = (const int*)d_in[15];
    float* out = (float*)d_out;

    // fp16 table (+ count/ticket zeroing) and CSR build
    k_tofp16<<<(N_NODES * 64 / 8) / 256, 256>>>(uw, ew);
    k_count<<<(N_EDGES / 4) / 256, 256>>>(target);
    k_scan1<<<SCAN_BLOCKS, 1024>>>();
    k_scan3<<<SCAN_BLOCKS, 1024>>>();
    k_scatter<<<(N_EDGES / 4) / 256, 256>>>(target, neighbor, values);

    // Layer 1
    k_gather<1><<<N_NODES / 8, 256>>>();
    k_dense<1><<<N_NODES / 64, 256>>>(W1a, b1a, W2a, b2a);

    // Layer 2
    k_gather<2><<<N_NODES / 8, 256>>>();
    k_dense<2><<<N_NODES / 64, 256>>>(W1b, b1b, W2b, b2b);

    // Scores
    k_score<<<(BATCH * 32) / 256, 256>>>(uw, ew, uid, pid, nid, out);
}